// round 8
// baseline (speedup 1.0000x reference)
#include <cuda_runtime.h>

// CrossAttMultiplexer collapses analytically:
//   out[n,i] = v[n,i] * sum_j softmax(...)[n,i,j] = s[n,i] * WV[0]
// Pure HBM stream: read s (6.29MB), write out (6.29MB).
//
// R8: REPLICATION RUN of the R5 config (sole sub-6.85 result: 6.624us).
// Seven diverse configs cluster at 6.85-6.88 (fixed T_ovh + graph-replay
// floor); this verifies whether R5's 592-CTA predicated-batch shape is a
// real effect or noise before committing a final kernel.

#define THREADS 256
#define BATCH   4

__global__ void __launch_bounds__(THREADS)
scale_stream_kernel(const float4* __restrict__ s4,
                    const float* __restrict__ WV,
                    float4* __restrict__ out4,
                    int n4) {
    const float wv = __ldg(WV);
    const int stride = gridDim.x * THREADS;
    int idx = blockIdx.x * THREADS + threadIdx.x;

    for (int base = idx; base < n4; base += BATCH * stride) {
        float4 v[BATCH];
        int   id[BATCH];
        bool   p[BATCH];
#pragma unroll
        for (int u = 0; u < BATCH; u++) {
            id[u] = base + u * stride;
            p[u]  = id[u] < n4;
            if (p[u]) v[u] = __ldcs(&s4[id[u]]);   // front-batched, evict-first
        }
#pragma unroll
        for (int u = 0; u < BATCH; u++) {
            if (p[u]) {
                v[u].x *= wv; v[u].y *= wv; v[u].z *= wv; v[u].w *= wv;
                __stcs(&out4[id[u]], v[u]);        // streaming store
            }
        }
    }
}

// Scalar fallback for n not divisible by 4.
__global__ void scale_generic_kernel(const float* __restrict__ s,
                                     const float* __restrict__ WV,
                                     float* __restrict__ out, int n) {
    const float wv = WV[0];
    for (int i = blockIdx.x * blockDim.x + threadIdx.x; i < n;
         i += gridDim.x * blockDim.x)
        out[i] = __ldcs(&s[i]) * wv;
}

extern "C" void kernel_launch(void* const* d_in, const int* in_sizes, int n_in,
                              void* d_out, int out_size) {
    // metadata order: x, s, WQ, WK, WV
    const float* s  = (const float*)d_in[1];
    const float* WV = (const float*)d_in[4];
    float* out = (float*)d_out;

    int n = out_size;
    if ((n & 3) == 0) {
        int n4 = n >> 2;                       // 393,216
        int blocks = 592;                      // 4 CTAs/SM * 148 SMs, one wave
        int needed = (n4 + THREADS - 1) / THREADS;
        if (blocks > needed) blocks = needed;  // tiny-input safety
        scale_stream_kernel<<<blocks, THREADS>>>((const float4*)s, WV,
                                                 (float4*)out, n4);
    } else {
        int blocks = (n + 255) / 256;
        if (blocks > 1184) blocks = 1184;
        scale_generic_kernel<<<blocks, 256>>>(s, WV, out, n);
    }
}